// round 11
// baseline (speedup 1.0000x reference)
#include <cuda_runtime.h>

#define B   32
#define CI  64
#define CO  128
#define KK  3
#define LL  8192

#define ZTL 256
#define ZNT 256
#define CG  4
#define CPG (CI / CG)    // 16
#define GT  (ZNT / CG)   // 64

#define YTL 128
#define YNT 256

__device__ float g_S[B * CI];
__device__ float g_win[B * CI * KK];
__device__ float g_wout[B * CO];
__device__ float g_bias[B * CO];
__device__ float g_z[B][LL];
__device__ unsigned int g_cnt[B];   // zero-init; atomicInc(,63) self-resets

// ---------------------------------------------------------------------------
// Kernel 1 (fused): per-(b,c) row sums + last-block-per-batch maker math.
// 2048 blocks x 128 threads.
// ---------------------------------------------------------------------------
__global__ __launch_bounds__(128) void rowsum_maker_kernel(
        const float* __restrict__ x,
        const float* __restrict__ Wk,
        const float* __restrict__ Win,
        const float* __restrict__ Wout,
        const float* __restrict__ Wbias) {
    const int row = blockIdx.x;          // b*64 + c
    const int b = row >> 6;
    const int tid = threadIdx.x;
    const int wid = tid >> 5;
    const int lane = tid & 31;

    // ---- row sum ----
    const float4* p = reinterpret_cast<const float4*>(x + (size_t)row * LL);
    float4 v[16];
#pragma unroll
    for (int j = 0; j < 16; j++) v[j] = p[tid + j * 128];

    float s = 0.f;
#pragma unroll
    for (int j = 0; j < 16; j++) s += (v[j].x + v[j].y) + (v[j].z + v[j].w);

#pragma unroll
    for (int off = 16; off > 0; off >>= 1)
        s += __shfl_xor_sync(0xffffffffu, s, off);

    __shared__ float wsum[4];
    __shared__ int is_last;
    if (lane == 0) wsum[wid] = s;
    __syncthreads();

    if (tid == 0) {
        g_S[row] = (wsum[0] + wsum[1]) + (wsum[2] + wsum[3]);
        __threadfence();
        unsigned int old = atomicInc(&g_cnt[b], CI - 1);  // wraps 63 -> 0
        is_last = (old == CI - 1);
    }
    __syncthreads();
    if (!is_last) return;

    // ---- maker phase (one block per batch; 128 threads) ----
    __shared__ float kern[CI * KK];
    __shared__ float sS[CI], sx0[CI], sxl[CI];

    if (tid < CI) {
        sS[tid] = g_S[b * CI + tid];
        const float* xb = x + ((size_t)b * CI + tid) * LL;
        sx0[tid] = xb[0];
        sxl[tid] = xb[LL - 1];
    }
    __syncthreads();

    for (int i = tid; i < CI * KK; i += 128) {
        int c = i / KK;
        float S = sS[c];
        float t0 = S - sxl[c];
        float t2 = S - sx0[c];
        kern[i] = (Wk[i * 3 + 0] * t0 + Wk[i * 3 + 1] * S +
                   Wk[i * 3 + 2] * t2) * (1.0f / LL);
    }
    __syncthreads();

    // w_in: 192 outputs, 64-dot each
    for (int i = tid; i < CI * KK; i += 128) {
        int o = i / KK, k = i % KK;
        float acc = 0.f;
#pragma unroll 8
        for (int c = 0; c < CI; c++) acc += kern[c * KK + k] * Win[o * CI + c];
        g_win[b * CI * KK + i] = acc;
    }

    // w_out / bias: 4 warps x 32 o's, lane-parallel coalesced dot
    for (int j = 0; j < CO / 4; j++) {
        int o = wid * (CO / 4) + j;
        const float* wo_row = Wout  + (size_t)o * (CI * KK);
        const float* wb_row = Wbias + (size_t)o * (CI * KK);
        float aco = 0.f, acb = 0.f;
#pragma unroll
        for (int i = lane; i < CI * KK; i += 32) {
            float kv = kern[i];
            aco = __fmaf_rn(kv, wo_row[i], aco);
            acb = __fmaf_rn(kv, wb_row[i], acb);
        }
#pragma unroll
        for (int off = 16; off > 0; off >>= 1) {
            aco += __shfl_xor_sync(0xffffffffu, aco, off);
            acb += __shfl_xor_sync(0xffffffffu, acb, off);
        }
        if (lane == 0) {
            g_wout[b * CO + o] = aco;
            g_bias[b * CO + o] = acb;
        }
    }
}

// ---------------------------------------------------------------------------
// Kernel 2: z, scatter formulation. Grid (32,32) x 256 threads.
// ---------------------------------------------------------------------------
__global__ __launch_bounds__(ZNT) void z_kernel(const float* __restrict__ x) {
    __shared__ float zp[CG][ZTL];
    __shared__ float edgeL[CG][GT];
    __shared__ float edgeR[CG][GT];
    __shared__ float swin[CI * KK];

    const int b = blockIdx.y;
    const int lbase = blockIdx.x * ZTL;
    const int tid = threadIdx.x;
    const int g = tid >> 6;
    const int t = tid & (GT - 1);
    const int l0 = lbase + t * 4;

    if (tid < CI * KK) swin[tid] = g_win[b * CI * KK + tid];
    __syncthreads();

    const float* xb = x + ((size_t)b * CI + g * CPG) * LL;
    float aL = 0.f, a0 = 0.f, a1 = 0.f, a2 = 0.f, a3 = 0.f, aR = 0.f;

#pragma unroll 4
    for (int c = 0; c < CPG; c++) {
        const float* xc = xb + (size_t)c * LL;
        float4 v = *reinterpret_cast<const float4*>(xc + l0);

        const float* w = swin + (g * CPG + c) * KK;
        float w0 = w[0], w1 = w[1], w2 = w[2];

        aL = __fmaf_rn(w2, v.x, aL);
        a0 = __fmaf_rn(w1, v.x, __fmaf_rn(w2, v.y, a0));
        a1 = __fmaf_rn(w0, v.x, __fmaf_rn(w1, v.y, __fmaf_rn(w2, v.z, a1)));
        a2 = __fmaf_rn(w0, v.y, __fmaf_rn(w1, v.z, __fmaf_rn(w2, v.w, a2)));
        a3 = __fmaf_rn(w0, v.z, __fmaf_rn(w1, v.w, a3));
        aR = __fmaf_rn(w0, v.w, aR);
    }

    if (t == 0 && l0 > 0) {
#pragma unroll
        for (int c = 0; c < CPG; c++)
            a0 = __fmaf_rn(swin[(g * CPG + c) * KK + 0],
                           xb[(size_t)c * LL + l0 - 1], a0);
    }
    if (t == GT - 1 && l0 + 4 < LL) {
#pragma unroll
        for (int c = 0; c < CPG; c++)
            a3 = __fmaf_rn(swin[(g * CPG + c) * KK + 2],
                           xb[(size_t)c * LL + l0 + 4], a3);
    }

    *reinterpret_cast<float4*>(&zp[g][t * 4]) = make_float4(a0, a1, a2, a3);
    edgeL[g][t] = aL;
    edgeR[g][t] = aR;
    __syncthreads();

    if (tid < ZTL / 4) {
        int j = tid;
        float4 s = make_float4(0.f, 0.f, 0.f, 0.f);
#pragma unroll
        for (int gg = 0; gg < CG; gg++) {
            float4 a = reinterpret_cast<const float4*>(zp[gg])[j];
            s.x += a.x; s.y += a.y; s.z += a.z; s.w += a.w;
            if (j > 0)      s.x += edgeR[gg][j - 1];
            if (j < GT - 1) s.w += edgeL[gg][j + 1];
        }
        reinterpret_cast<float4*>(&g_z[b][lbase])[j] = s;
    }
}

// ---------------------------------------------------------------------------
// Kernel 3: y = wout*z + bias. Grid (64, 32) x 256 threads.
// ---------------------------------------------------------------------------
__global__ __launch_bounds__(YNT) void y_kernel(float* __restrict__ y) {
    __shared__ float sz[YTL];
    __shared__ float swout[CO];
    __shared__ float sbias[CO];

    const int b = blockIdx.y;
    const int lbase = blockIdx.x * YTL;
    const int tid = threadIdx.x;

    if (tid < CO) {
        swout[tid] = g_wout[b * CO + tid];
        sbias[tid] = g_bias[b * CO + tid];
    }
    if (tid < YTL / 4)
        reinterpret_cast<float4*>(sz)[tid] =
            reinterpret_cast<const float4*>(&g_z[b][lbase])[tid];
    __syncthreads();

    const int l4 = tid & 31;
    const int o0 = tid >> 5;
    const float4 zv = reinterpret_cast<const float4*>(sz)[l4];

    float4* p = reinterpret_cast<float4*>(
        y + (size_t)b * CO * LL + (size_t)o0 * LL + lbase) + l4;

#pragma unroll
    for (int k = 0; k < CO / 8; k++) {
        int o = o0 + k * 8;
        float wo = swout[o], bi = sbias[o];
        float4 r;
        r.x = __fmaf_rn(wo, zv.x, bi);
        r.y = __fmaf_rn(wo, zv.y, bi);
        r.z = __fmaf_rn(wo, zv.z, bi);
        r.w = __fmaf_rn(wo, zv.w, bi);
        __stcs(p, r);
        p += 2 * LL;
    }
}

// ---------------------------------------------------------------------------
extern "C" void kernel_launch(void* const* d_in, const int* in_sizes, int n_in,
                              void* d_out, int out_size) {
    const float* x     = (const float*)d_in[0];
    const float* Wk    = (const float*)d_in[1];
    const float* Win   = (const float*)d_in[2];
    const float* Wout  = (const float*)d_in[3];
    const float* Wbias = (const float*)d_in[4];
    float* y = (float*)d_out;

    rowsum_maker_kernel<<<B * CI, 128>>>(x, Wk, Win, Wout, Wbias);
    dim3 zgrid(LL / ZTL, B);
    z_kernel<<<zgrid, ZNT>>>(x);
    dim3 ygrid(LL / YTL, B);
    y_kernel<<<ygrid, YNT>>>(y);
}

// round 13
// speedup vs baseline: 1.3219x; 1.3219x over previous
#include <cuda_runtime.h>

#define B   32
#define CI  64
#define CO  128
#define KK  3
#define LL  8192

#define ZTL 128
#define ZNT 256
#define CG  8
#define CPG (CI / CG)    // 8 channels per group
#define GT  (ZNT / CG)   // 32 threads per group

#define YTL 128
#define YNT 256

#define MPART 4
#define OPP  (CO / MPART)

__device__ float g_S[B * CI];
__device__ float g_win[B * CI * KK];
__device__ float g_wout[B * CO];
__device__ float g_bias[B * CO];
__device__ float g_z[B][LL];

// ---------------------------------------------------------------------------
// Kernel 1: per-(b,c) row sums. 2048 blocks x 128 threads, 16 float4 each.
// ---------------------------------------------------------------------------
__global__ __launch_bounds__(128) void rowsum_kernel(const float* __restrict__ x) {
    const int row = blockIdx.x;
    const float4* p = reinterpret_cast<const float4*>(x + (size_t)row * LL);

    float4 v[16];
#pragma unroll
    for (int j = 0; j < 16; j++) v[j] = p[threadIdx.x + j * 128];

    float s = 0.f;
#pragma unroll
    for (int j = 0; j < 16; j++) s += (v[j].x + v[j].y) + (v[j].z + v[j].w);

#pragma unroll
    for (int off = 16; off > 0; off >>= 1)
        s += __shfl_xor_sync(0xffffffffu, s, off);

    __shared__ float wsum[4];
    if ((threadIdx.x & 31) == 0) wsum[threadIdx.x >> 5] = s;
    __syncthreads();
    if (threadIdx.x == 0)
        g_S[row] = (wsum[0] + wsum[1]) + (wsum[2] + wsum[3]);
}

// ---------------------------------------------------------------------------
// Kernel 2: maker. Grid (4, 32) x 256 threads.
// ---------------------------------------------------------------------------
__global__ __launch_bounds__(256) void maker_kernel(const float* __restrict__ x,
                             const float* __restrict__ Wk,
                             const float* __restrict__ Win,
                             const float* __restrict__ Wout,
                             const float* __restrict__ Wbias) {
    const int b = blockIdx.y;
    const int part = blockIdx.x;
    const int tid = threadIdx.x;
    const int wid = tid >> 5;
    const int lane = tid & 31;

    __shared__ float kern[CI * KK];
    __shared__ float sS[CI], sx0[CI], sxl[CI];

    if (tid < CI) {
        sS[tid] = g_S[b * CI + tid];
        const float* xb = x + ((size_t)b * CI + tid) * LL;
        sx0[tid] = xb[0];
        sxl[tid] = xb[LL - 1];
    }
    __syncthreads();

    if (tid < CI * KK) {
        int c = tid / KK;
        float S = sS[c];
        float t0 = S - sxl[c];
        float t2 = S - sx0[c];
        kern[tid] = (Wk[tid * 3 + 0] * t0 + Wk[tid * 3 + 1] * S +
                     Wk[tid * 3 + 2] * t2) * (1.0f / LL);
    }
    __syncthreads();

    if (part == 0 && tid < CI * KK) {
        int o = tid / KK, k = tid % KK;
        float acc = 0.f;
#pragma unroll 8
        for (int c = 0; c < CI; c++) acc += kern[c * KK + k] * Win[o * CI + c];
        g_win[b * CI * KK + tid] = acc;
    }

#pragma unroll
    for (int j = 0; j < OPP / 8; j++) {
        int o = part * OPP + wid * (OPP / 8) + j;
        const float* wo_row = Wout  + (size_t)o * (CI * KK);
        const float* wb_row = Wbias + (size_t)o * (CI * KK);
        float aco = 0.f, acb = 0.f;
#pragma unroll
        for (int i = lane; i < CI * KK; i += 32) {
            float kv = kern[i];
            aco = __fmaf_rn(kv, wo_row[i], aco);
            acb = __fmaf_rn(kv, wb_row[i], acb);
        }
#pragma unroll
        for (int off = 16; off > 0; off >>= 1) {
            aco += __shfl_xor_sync(0xffffffffu, aco, off);
            acb += __shfl_xor_sync(0xffffffffu, acb, off);
        }
        if (lane == 0) {
            g_wout[b * CO + o] = aco;
            g_bias[b * CO + o] = acb;
        }
    }
}

// ---------------------------------------------------------------------------
// Kernel 3: z, scatter formulation. Grid (64,32) x 256 threads.
// 8 c-groups x 8 channels; each thread: 8 LDG.128 + 6 FMA/channel.
// ---------------------------------------------------------------------------
__global__ __launch_bounds__(ZNT) void z_kernel(const float* __restrict__ x) {
    __shared__ float zp[CG][ZTL];
    __shared__ float edgeL[CG][GT];
    __shared__ float edgeR[CG][GT];
    __shared__ float swin[CI * KK];

    const int b = blockIdx.y;
    const int lbase = blockIdx.x * ZTL;
    const int tid = threadIdx.x;
    const int g = tid / GT;
    const int t = tid % GT;
    const int l0 = lbase + t * 4;

    if (tid < CI * KK) swin[tid] = g_win[b * CI * KK + tid];
    __syncthreads();

    const float* xb = x + ((size_t)b * CI + g * CPG) * LL;
    float aL = 0.f, a0 = 0.f, a1 = 0.f, a2 = 0.f, a3 = 0.f, aR = 0.f;

#pragma unroll
    for (int c = 0; c < CPG; c++) {
        const float* xc = xb + (size_t)c * LL;
        float4 v = *reinterpret_cast<const float4*>(xc + l0);

        const float* w = swin + (g * CPG + c) * KK;
        float w0 = w[0], w1 = w[1], w2 = w[2];

        aL = __fmaf_rn(w2, v.x, aL);
        a0 = __fmaf_rn(w1, v.x, __fmaf_rn(w2, v.y, a0));
        a1 = __fmaf_rn(w0, v.x, __fmaf_rn(w1, v.y, __fmaf_rn(w2, v.z, a1)));
        a2 = __fmaf_rn(w0, v.y, __fmaf_rn(w1, v.z, __fmaf_rn(w2, v.w, a2)));
        a3 = __fmaf_rn(w0, v.z, __fmaf_rn(w1, v.w, a3));
        aR = __fmaf_rn(w0, v.w, aR);
    }

    // Block-boundary terms: group-edge threads only.
    if (t == 0 && l0 > 0) {
#pragma unroll
        for (int c = 0; c < CPG; c++)
            a0 = __fmaf_rn(swin[(g * CPG + c) * KK + 0],
                           xb[(size_t)c * LL + l0 - 1], a0);
    }
    if (t == GT - 1 && l0 + 4 < LL) {
#pragma unroll
        for (int c = 0; c < CPG; c++)
            a3 = __fmaf_rn(swin[(g * CPG + c) * KK + 2],
                           xb[(size_t)c * LL + l0 + 4], a3);
    }

    *reinterpret_cast<float4*>(&zp[g][t * 4]) = make_float4(a0, a1, a2, a3);
    edgeL[g][t] = aL;
    edgeR[g][t] = aR;
    __syncthreads();

    if (tid < ZTL / 4) {
        int j = tid;
        float4 s = make_float4(0.f, 0.f, 0.f, 0.f);
#pragma unroll
        for (int gg = 0; gg < CG; gg++) {
            float4 a = reinterpret_cast<const float4*>(zp[gg])[j];
            s.x += a.x; s.y += a.y; s.z += a.z; s.w += a.w;
            if (j > 0)      s.x += edgeR[gg][j - 1];
            if (j < GT - 1) s.w += edgeL[gg][j + 1];
        }
        reinterpret_cast<float4*>(&g_z[b][lbase])[j] = s;
    }
}

// ---------------------------------------------------------------------------
// Kernel 4: y = wout*z + bias. Grid (64, 32) x 256 threads.
// ---------------------------------------------------------------------------
__global__ __launch_bounds__(YNT) void y_kernel(float* __restrict__ y) {
    __shared__ float sz[YTL];
    __shared__ float swout[CO];
    __shared__ float sbias[CO];

    const int b = blockIdx.y;
    const int lbase = blockIdx.x * YTL;
    const int tid = threadIdx.x;

    if (tid < CO) {
        swout[tid] = g_wout[b * CO + tid];
        sbias[tid] = g_bias[b * CO + tid];
    }
    if (tid < YTL / 4)
        reinterpret_cast<float4*>(sz)[tid] =
            reinterpret_cast<const float4*>(&g_z[b][lbase])[tid];
    __syncthreads();

    const int l4 = tid & 31;
    const int o0 = tid >> 5;
    const float4 zv = reinterpret_cast<const float4*>(sz)[l4];

    float4* p = reinterpret_cast<float4*>(
        y + (size_t)b * CO * LL + (size_t)o0 * LL + lbase) + l4;

#pragma unroll
    for (int k = 0; k < CO / 8; k++) {
        int o = o0 + k * 8;
        float wo = swout[o], bi = sbias[o];
        float4 r;
        r.x = __fmaf_rn(wo, zv.x, bi);
        r.y = __fmaf_rn(wo, zv.y, bi);
        r.z = __fmaf_rn(wo, zv.z, bi);
        r.w = __fmaf_rn(wo, zv.w, bi);
        __stcs(p, r);
        p += 2 * LL;
    }
}

// ---------------------------------------------------------------------------
extern "C" void kernel_launch(void* const* d_in, const int* in_sizes, int n_in,
                              void* d_out, int out_size) {
    const float* x     = (const float*)d_in[0];
    const float* Wk    = (const float*)d_in[1];
    const float* Win   = (const float*)d_in[2];
    const float* Wout  = (const float*)d_in[3];
    const float* Wbias = (const float*)d_in[4];
    float* y = (float*)d_out;

    rowsum_kernel<<<B * CI, 128>>>(x);
    dim3 mgrid(MPART, B);
    maker_kernel<<<mgrid, 256>>>(x, Wk, Win, Wout, Wbias);
    dim3 zgrid(LL / ZTL, B);
    z_kernel<<<zgrid, ZNT>>>(x);
    dim3 ygrid(LL / YTL, B);
    y_kernel<<<ygrid, YNT>>>(y);
}

// round 16
// speedup vs baseline: 1.5349x; 1.1612x over previous
#include <cuda_runtime.h>

#define B   32
#define CI  64
#define CO  128
#define KK  3
#define LL  8192
#define NROW (B * CI)    // 2048

#define ZTL 256
#define ZNT 256
#define CG  4
#define CPG (CI / CG)    // 16
#define GT  (ZNT / CG)   // 64

#define YTL 128
#define YNT 256

#define MPART 4
#define OPP  (CO / MPART)

__device__ float g_S[NROW];
__device__ float g_win[B * CI * KK];
__device__ float g_wout[B * CO];
__device__ float g_bias[B * CO];
__device__ float g_z[B][LL];

// ---------------------------------------------------------------------------
// Kernel 1: per-(b,c) row sums. 1024 blocks x 256 threads, 2 rows per block
// (strided pairing: row = blockIdx.x + half*1024).
// ---------------------------------------------------------------------------
__global__ __launch_bounds__(256) void rowsum_kernel(const float* __restrict__ x) {
    const int tid = threadIdx.x;
    const int half = tid >> 7;              // 0 or 1
    const int ht = tid & 127;               // 0..127 within half
    const int row = blockIdx.x + half * (NROW / 2);

    const float4* p = reinterpret_cast<const float4*>(x + (size_t)row * LL);

    float4 v[16];
#pragma unroll
    for (int j = 0; j < 16; j++) v[j] = p[ht + j * 128];

    float s = 0.f;
#pragma unroll
    for (int j = 0; j < 16; j++) s += (v[j].x + v[j].y) + (v[j].z + v[j].w);

#pragma unroll
    for (int off = 16; off > 0; off >>= 1)
        s += __shfl_xor_sync(0xffffffffu, s, off);

    __shared__ float wsum[8];               // warps 0-3: half 0, warps 4-7: half 1
    if ((tid & 31) == 0) wsum[tid >> 5] = s;
    __syncthreads();
    if (ht == 0) {
        const float* w = wsum + half * 4;
        g_S[row] = (w[0] + w[1]) + (w[2] + w[3]);
    }
}

// ---------------------------------------------------------------------------
// Kernel 2: maker. Grid (4, 32) x 256 threads.
// ---------------------------------------------------------------------------
__global__ __launch_bounds__(256) void maker_kernel(const float* __restrict__ x,
                             const float* __restrict__ Wk,
                             const float* __restrict__ Win,
                             const float* __restrict__ Wout,
                             const float* __restrict__ Wbias) {
    const int b = blockIdx.y;
    const int part = blockIdx.x;
    const int tid = threadIdx.x;
    const int wid = tid >> 5;
    const int lane = tid & 31;

    __shared__ float kern[CI * KK];
    __shared__ float sS[CI], sx0[CI], sxl[CI];

    if (tid < CI) {
        sS[tid] = g_S[b * CI + tid];
        const float* xb = x + ((size_t)b * CI + tid) * LL;
        sx0[tid] = xb[0];
        sxl[tid] = xb[LL - 1];
    }
    __syncthreads();

    if (tid < CI * KK) {
        int c = tid / KK;
        float S = sS[c];
        float t0 = S - sxl[c];
        float t2 = S - sx0[c];
        kern[tid] = (Wk[tid * 3 + 0] * t0 + Wk[tid * 3 + 1] * S +
                     Wk[tid * 3 + 2] * t2) * (1.0f / LL);
    }
    __syncthreads();

    if (part == 0 && tid < CI * KK) {
        int o = tid / KK, k = tid % KK;
        float acc = 0.f;
#pragma unroll 8
        for (int c = 0; c < CI; c++) acc += kern[c * KK + k] * Win[o * CI + c];
        g_win[b * CI * KK + tid] = acc;
    }

#pragma unroll
    for (int j = 0; j < OPP / 8; j++) {
        int o = part * OPP + wid * (OPP / 8) + j;
        const float* wo_row = Wout  + (size_t)o * (CI * KK);
        const float* wb_row = Wbias + (size_t)o * (CI * KK);
        float aco = 0.f, acb = 0.f;
#pragma unroll
        for (int i = lane; i < CI * KK; i += 32) {
            float kv = kern[i];
            aco = __fmaf_rn(kv, wo_row[i], aco);
            acb = __fmaf_rn(kv, wb_row[i], acb);
        }
#pragma unroll
        for (int off = 16; off > 0; off >>= 1) {
            aco += __shfl_xor_sync(0xffffffffu, aco, off);
            acb += __shfl_xor_sync(0xffffffffu, acb, off);
        }
        if (lane == 0) {
            g_wout[b * CO + o] = aco;
            g_bias[b * CO + o] = acb;
        }
    }
}

// ---------------------------------------------------------------------------
// Kernel 3: z, scatter formulation. Grid (32,32) x 256 threads.
// ---------------------------------------------------------------------------
__global__ __launch_bounds__(ZNT) void z_kernel(const float* __restrict__ x) {
    __shared__ float zp[CG][ZTL];
    __shared__ float edgeL[CG][GT];
    __shared__ float edgeR[CG][GT];
    __shared__ float swin[CI * KK];

    const int b = blockIdx.y;
    const int lbase = blockIdx.x * ZTL;
    const int tid = threadIdx.x;
    const int g = tid >> 6;
    const int t = tid & (GT - 1);
    const int l0 = lbase + t * 4;

    if (tid < CI * KK) swin[tid] = g_win[b * CI * KK + tid];
    __syncthreads();

    const float* xb = x + ((size_t)b * CI + g * CPG) * LL;
    float aL = 0.f, a0 = 0.f, a1 = 0.f, a2 = 0.f, a3 = 0.f, aR = 0.f;

#pragma unroll 4
    for (int c = 0; c < CPG; c++) {
        const float* xc = xb + (size_t)c * LL;
        float4 v = *reinterpret_cast<const float4*>(xc + l0);

        const float* w = swin + (g * CPG + c) * KK;
        float w0 = w[0], w1 = w[1], w2 = w[2];

        aL = __fmaf_rn(w2, v.x, aL);
        a0 = __fmaf_rn(w1, v.x, __fmaf_rn(w2, v.y, a0));
        a1 = __fmaf_rn(w0, v.x, __fmaf_rn(w1, v.y, __fmaf_rn(w2, v.z, a1)));
        a2 = __fmaf_rn(w0, v.y, __fmaf_rn(w1, v.z, __fmaf_rn(w2, v.w, a2)));
        a3 = __fmaf_rn(w0, v.z, __fmaf_rn(w1, v.w, a3));
        aR = __fmaf_rn(w0, v.w, aR);
    }

    if (t == 0 && l0 > 0) {
#pragma unroll
        for (int c = 0; c < CPG; c++)
            a0 = __fmaf_rn(swin[(g * CPG + c) * KK + 0],
                           xb[(size_t)c * LL + l0 - 1], a0);
    }
    if (t == GT - 1 && l0 + 4 < LL) {
#pragma unroll
        for (int c = 0; c < CPG; c++)
            a3 = __fmaf_rn(swin[(g * CPG + c) * KK + 2],
                           xb[(size_t)c * LL + l0 + 4], a3);
    }

    *reinterpret_cast<float4*>(&zp[g][t * 4]) = make_float4(a0, a1, a2, a3);
    edgeL[g][t] = aL;
    edgeR[g][t] = aR;
    __syncthreads();

    if (tid < ZTL / 4) {
        int j = tid;
        float4 s = make_float4(0.f, 0.f, 0.f, 0.f);
#pragma unroll
        for (int gg = 0; gg < CG; gg++) {
            float4 a = reinterpret_cast<const float4*>(zp[gg])[j];
            s.x += a.x; s.y += a.y; s.z += a.z; s.w += a.w;
            if (j > 0)      s.x += edgeR[gg][j - 1];
            if (j < GT - 1) s.w += edgeL[gg][j + 1];
        }
        reinterpret_cast<float4*>(&g_z[b][lbase])[j] = s;
    }
}

// ---------------------------------------------------------------------------
// Kernel 4: y = wout*z + bias. Grid (64, 32) x 256 threads.
// ---------------------------------------------------------------------------
__global__ __launch_bounds__(YNT) void y_kernel(float* __restrict__ y) {
    __shared__ float sz[YTL];
    __shared__ float swout[CO];
    __shared__ float sbias[CO];

    const int b = blockIdx.y;
    const int lbase = blockIdx.x * YTL;
    const int tid = threadIdx.x;

    if (tid < CO) {
        swout[tid] = g_wout[b * CO + tid];
        sbias[tid] = g_bias[b * CO + tid];
    }
    if (tid < YTL / 4)
        reinterpret_cast<float4*>(sz)[tid] =
            reinterpret_cast<const float4*>(&g_z[b][lbase])[tid];
    __syncthreads();

    const int l4 = tid & 31;
    const int o0 = tid >> 5;
    const float4 zv = reinterpret_cast<const float4*>(sz)[l4];

    float4* p = reinterpret_cast<float4*>(
        y + (size_t)b * CO * LL + (size_t)o0 * LL + lbase) + l4;

#pragma unroll
    for (int k = 0; k < CO / 8; k++) {
        int o = o0 + k * 8;
        float wo = swout[o], bi = sbias[o];
        float4 r;
        r.x = __fmaf_rn(wo, zv.x, bi);
        r.y = __fmaf_rn(wo, zv.y, bi);
        r.z = __fmaf_rn(wo, zv.z, bi);
        r.w = __fmaf_rn(wo, zv.w, bi);
        __stcs(p, r);
        p += 2 * LL;
    }
}

// ---------------------------------------------------------------------------
extern "C" void kernel_launch(void* const* d_in, const int* in_sizes, int n_in,
                              void* d_out, int out_size) {
    const float* x     = (const float*)d_in[0];
    const float* Wk    = (const float*)d_in[1];
    const float* Win   = (const float*)d_in[2];
    const float* Wout  = (const float*)d_in[3];
    const float* Wbias = (const float*)d_in[4];
    float* y = (float*)d_out;

    rowsum_kernel<<<NROW / 2, 256>>>(x);
    dim3 mgrid(MPART, B);
    maker_kernel<<<mgrid, 256>>>(x, Wk, Win, Wout, Wbias);
    dim3 zgrid(LL / ZTL, B);
    z_kernel<<<zgrid, ZNT>>>(x);
    dim3 ygrid(LL / YTL, B);
    y_kernel<<<ygrid, YNT>>>(y);
}